// round 12
// baseline (speedup 1.0000x reference)
#include <cuda_runtime.h>
#include <math.h>

// Shapes (fixed by the problem)
#define Bc 4
#define Hc 16
#define Sc 1024
#define Dc 64

// Tiling
#define BQ 128
#define BKT 64
#define DPAD 68      // 64 + 4 pad (floats) — float4-aligned rows, breaks bank patterns
#define BKPAD 68
#define NTHREADS 256

// Mask layout flag: 0 = 32-bit words (int32 or float32 bool), 1 = 1-byte bools
__device__ int g_mask_byte_mode;

__global__ void detect_mask_dtype_kernel(const unsigned int* __restrict__ m) {
    __shared__ int bad;
    if (threadIdx.x == 0) bad = 0;
    __syncthreads();
    // int32 bools  -> words in {0,1}
    // float32 bools-> words in {0, 0x3F800000}
    // u8 bools     -> packed words like 0x01010101 appear w.p. 7/8 per word
    int local_bad = 0;
    for (int i = threadIdx.x; i < 8192; i += blockDim.x) {
        unsigned int w = m[i];
        if (w != 0u && w != 1u && w != 0x3F800000u) local_bad = 1;
    }
    if (local_bad) bad = 1;
    __syncthreads();
    if (threadIdx.x == 0) g_mask_byte_mode = bad;
}

__global__ __launch_bounds__(NTHREADS, 1)
void attn_flash_kernel(const float* __restrict__ Q,
                       const float* __restrict__ K,
                       const float* __restrict__ V,
                       const void* __restrict__ MSK,
                       const float* __restrict__ TW,
                       const float* __restrict__ DU,
                       float* __restrict__ O) {
    extern __shared__ float sm[];
    float* sQ = sm;                          // BQ  x DPAD
    float* sK = sQ + BQ * DPAD;              // BKT x DPAD
    float* sV = sK + BKT * DPAD;             // BKT x DPAD
    float* sP = sV + BKT * DPAD;             // BQ  x BKPAD
    float* sMx = sP + BQ * BKPAD;            // BQ running max
    float* sZ  = sMx + BQ;                   // BQ running denom
    float* sC  = sZ + BQ;                    // BQ correction factor

    const int t  = threadIdx.x;
    const int bh = blockIdx.x >> 3;          // Sc/BQ == 8 q-tiles
    const int q0 = (blockIdx.x & 7) * BQ;

    const int mask_bytes = g_mask_byte_mode; // uniform across grid

    const size_t qkvbase = (size_t)bh * Sc * Dc;
    const size_t mbase   = (size_t)bh * Sc * Sc;
    const float* Qb = Q + qkvbase;
    const float* Kb = K + qkvbase;
    const float* Vb = V + qkvbase;
    const unsigned int*  MbW = (const unsigned int*)MSK + mbase;   // word bools
    const unsigned char* MbB = (const unsigned char*)MSK + mbase;  // byte bools
    const float* Tb = TW + mbase;
    const float* Ub = DU + mbase;
    float* Ob = O + qkvbase;

    // ---- Load Q tile (coalesced float4) ----
    for (int i = t; i < BQ * (Dc / 4); i += NTHREADS) {
        int q = i >> 4, d4 = i & 15;
        ((float4*)(sQ + q * DPAD))[d4] =
            ((const float4*)(Qb + (size_t)(q0 + q) * Dc))[d4];
    }
    if (t < BQ) { sMx[t] = -INFINITY; sZ[t] = 0.f; }

    const int lane = t & 31;
    const int w    = t >> 5;                 // 8 warps

    // Phase-D mapping: warp w owns q rows [16w, 16w+16); lane owns 8 rows
    // (upper/lower half by lane>>4) x one float4 d-chunk (lane&15).
    const int qb = (w << 4) + ((lane >> 4) << 3);
    const int dc = lane & 15;
    float4 acc[8];
    #pragma unroll
    for (int i = 0; i < 8; i++) acc[i] = make_float4(0.f, 0.f, 0.f, 0.f);

    // Phase-A mapping: 8x4 micro-tile; q rows tq..tq+7, k cols u+16j (striped)
    const int tq = (t >> 4) << 3;            // 0,8,...,120
    const int u  = t & 15;

    __syncthreads();

    const float scale = 0.125f;              // 1/sqrt(64)

    for (int kt = 0; kt < Sc / BKT; kt++) {
        const int k0 = kt * BKT;

        // ---- Load K,V tiles ----
        for (int i = t; i < BKT * (Dc / 4); i += NTHREADS) {
            int k = i >> 4, d4 = i & 15;
            ((float4*)(sK + k * DPAD))[d4] =
                ((const float4*)(Kb + (size_t)(k0 + k) * Dc))[d4];
            ((float4*)(sV + k * DPAD))[d4] =
                ((const float4*)(Vb + (size_t)(k0 + k) * Dc))[d4];
        }
        __syncthreads();

        // ---- Phase A: S = Q K^T (8x4 micro-tile per thread) ----
        {
            float s[8][4];
            #pragma unroll
            for (int i = 0; i < 8; i++)
                #pragma unroll
                for (int j = 0; j < 4; j++) s[i][j] = 0.f;

            #pragma unroll 4
            for (int d4 = 0; d4 < 16; d4++) {
                float4 kv0 = ((const float4*)(sK + (u +  0) * DPAD))[d4];
                float4 kv1 = ((const float4*)(sK + (u + 16) * DPAD))[d4];
                float4 kv2 = ((const float4*)(sK + (u + 32) * DPAD))[d4];
                float4 kv3 = ((const float4*)(sK + (u + 48) * DPAD))[d4];
                #pragma unroll
                for (int i = 0; i < 8; i++) {
                    float4 qv = ((const float4*)(sQ + (tq + i) * DPAD))[d4];
                    s[i][0] += qv.x*kv0.x + qv.y*kv0.y + qv.z*kv0.z + qv.w*kv0.w;
                    s[i][1] += qv.x*kv1.x + qv.y*kv1.y + qv.z*kv1.z + qv.w*kv1.w;
                    s[i][2] += qv.x*kv2.x + qv.y*kv2.y + qv.z*kv2.z + qv.w*kv2.w;
                    s[i][3] += qv.x*kv3.x + qv.y*kv3.y + qv.z*kv3.z + qv.w*kv3.w;
                }
            }

            if (mask_bytes == 0) {
                #pragma unroll
                for (int i = 0; i < 8; i++) {
                    const unsigned int* mrow = MbW + (size_t)(q0 + tq + i) * Sc + k0;
                    float* prow = sP + (tq + i) * BKPAD;
                    #pragma unroll
                    for (int j = 0; j < 4; j++) {
                        int k = u + 16 * j;
                        prow[k] = mrow[k] ? -1e9f : s[i][j] * scale;
                    }
                }
            } else {
                #pragma unroll
                for (int i = 0; i < 8; i++) {
                    const unsigned char* mrow = MbB + (size_t)(q0 + tq + i) * Sc + k0;
                    float* prow = sP + (tq + i) * BKPAD;
                    #pragma unroll
                    for (int j = 0; j < 4; j++) {
                        int k = u + 16 * j;
                        prow[k] = mrow[k] ? -1e9f : s[i][j] * scale;
                    }
                }
            }
        }
        __syncthreads();

        // ---- Phase B: per-row tile max (2 lanes per row), running max ----
        {
            int r  = t >> 1;
            int p2 = t & 1;
            float mx = -INFINITY;
            #pragma unroll
            for (int k = p2; k < BKT; k += 2) mx = fmaxf(mx, sP[r * BKPAD + k]);
            mx = fmaxf(mx, __shfl_xor_sync(0xffffffffu, mx, 1));
            if (p2 == 0) {
                float mold = sMx[r];
                float mnew = fmaxf(mold, mx);
                sMx[r] = mnew;
                sC[r]  = __expf(mold - mnew);   // 0 on first tile (mold=-inf)
            }
        }
        __syncthreads();

        // ---- Phase C: p=exp(s-m); Z update; fold tw * dropout into P ----
        // warp w owns rows 16w..16w+15; lanes stride k -> coalesced tw/du loads
        {
            #pragma unroll
            for (int r16 = 0; r16 < 16; r16++) {
                int r = (w << 4) + r16;
                float mnew = sMx[r];
                const float* trow = Tb + (size_t)(q0 + r) * Sc + k0;
                const float* urow = Ub + (size_t)(q0 + r) * Sc + k0;
                float sum = 0.f;
                #pragma unroll
                for (int h = 0; h < 2; h++) {
                    int k = lane + 32 * h;
                    float p = __expf(sP[r * BKPAD + k] - mnew);
                    sum += p;
                    float keep = (urow[k] >= 0.5f) ? 2.0f : 0.0f;
                    sP[r * BKPAD + k] = p * trow[k] * keep;
                }
                #pragma unroll
                for (int off = 16; off; off >>= 1)
                    sum += __shfl_xor_sync(0xffffffffu, sum, off);
                if (lane == 0) sZ[r] = sZ[r] * sC[r] + sum;
            }
        }
        __syncthreads();

        // ---- Phase D: acc = acc*c + P @ V (8 q-rows x 1 chunk per lane) ----
        {
            #pragma unroll
            for (int i = 0; i < 8; i++) {
                float c = sC[qb + i];
                acc[i].x *= c; acc[i].y *= c; acc[i].z *= c; acc[i].w *= c;
            }
            #pragma unroll 4
            for (int k4 = 0; k4 < BKT / 4; k4++) {
                float4 v0 = ((const float4*)(sV + (4*k4 + 0) * DPAD))[dc];
                float4 v1 = ((const float4*)(sV + (4*k4 + 1) * DPAD))[dc];
                float4 v2 = ((const float4*)(sV + (4*k4 + 2) * DPAD))[dc];
                float4 v3 = ((const float4*)(sV + (4*k4 + 3) * DPAD))[dc];
                #pragma unroll
                for (int i = 0; i < 8; i++) {
                    float4 p = ((const float4*)(sP + (qb + i) * BKPAD))[k4];
                    acc[i].x += p.x*v0.x + p.y*v1.x + p.z*v2.x + p.w*v3.x;
                    acc[i].y += p.x*v0.y + p.y*v1.y + p.z*v2.y + p.w*v3.y;
                    acc[i].z += p.x*v0.z + p.y*v1.z + p.z*v2.z + p.w*v3.z;
                    acc[i].w += p.x*v0.w + p.y*v1.w + p.z*v2.w + p.w*v3.w;
                }
            }
        }
        __syncthreads();
    }

    // ---- Epilogue: out = acc / Z ----
    #pragma unroll
    for (int i = 0; i < 8; i++) {
        float inv = 1.0f / sZ[qb + i];
        float4 o = acc[i];
        o.x *= inv; o.y *= inv; o.z *= inv; o.w *= inv;
        ((float4*)(Ob + (size_t)(q0 + qb + i) * Dc))[dc] = o;
    }
}

extern "C" void kernel_launch(void* const* d_in, const int* in_sizes, int n_in,
                              void* d_out, int out_size) {
    const float* Q  = (const float*)d_in[0];
    const float* K  = (const float*)d_in[1];
    const float* V  = (const float*)d_in[2];
    const void*  M  = d_in[3];               // bool mask — dtype detected on device
    const float* TW = (const float*)d_in[4];
    const float* DU = (const float*)d_in[5];
    float* O = (float*)d_out;

    const size_t smem_bytes =
        (size_t)(BQ * DPAD + 2 * BKT * DPAD + BQ * BKPAD + 3 * BQ) * sizeof(float);

    cudaFuncSetAttribute(attn_flash_kernel,
                         cudaFuncAttributeMaxDynamicSharedMemorySize,
                         (int)smem_bytes);

    // 1) Detect mask storage layout (word-bool vs byte-bool).
    detect_mask_dtype_kernel<<<1, 256>>>((const unsigned int*)M);

    // 2) Flash attention, one CTA per (b, h, 128-row q-tile).
    dim3 grid(Bc * Hc * (Sc / BQ));   // 512 blocks
    attn_flash_kernel<<<grid, NTHREADS, smem_bytes>>>(Q, K, V, M, TW, DU, O);
}

// round 13
// speedup vs baseline: 1.4157x; 1.4157x over previous
#include <cuda_runtime.h>
#include <math.h>

// Shapes (fixed by the problem)
#define Bc 4
#define Hc 16
#define Sc 1024
#define Dc 64

// Tiling
#define BQ 128
#define BKT 64
#define DPAD 68      // 64 + 4 pad (floats) — float4-aligned rows, breaks bank patterns
#define BKPAD 68
#define NTHREADS 256

// Mask layout flag: 0 = 32-bit words (int32 or float32 bool), 1 = 1-byte bools
__device__ int g_mask_byte_mode;

__global__ void detect_mask_dtype_kernel(const unsigned int* __restrict__ m) {
    __shared__ int bad;
    if (threadIdx.x == 0) bad = 0;
    __syncthreads();
    // int32 bools  -> words in {0,1}
    // float32 bools-> words in {0, 0x3F800000}
    // u8 bools     -> packed words like 0x01010101 appear w.p. 7/8 per word
    int local_bad = 0;
    for (int i = threadIdx.x; i < 8192; i += blockDim.x) {
        unsigned int w = m[i];
        if (w != 0u && w != 1u && w != 0x3F800000u) local_bad = 1;
    }
    if (local_bad) bad = 1;
    __syncthreads();
    if (threadIdx.x == 0) g_mask_byte_mode = bad;
}

// minBlocksPerMultiprocessor=2 caps regs at 128 -> 2 CTAs (16 warps) per SM.
__global__ __launch_bounds__(NTHREADS, 2)
void attn_flash_kernel(const float* __restrict__ Q,
                       const float* __restrict__ K,
                       const float* __restrict__ V,
                       const void* __restrict__ MSK,
                       const float* __restrict__ TW,
                       const float* __restrict__ DU,
                       float* __restrict__ O) {
    extern __shared__ float sm[];
    float* sQ = sm;                          // BQ  x DPAD
    float* sK = sQ + BQ * DPAD;              // BKT x DPAD
    float* sV = sK + BKT * DPAD;             // BKT x DPAD
    float* sP = sV + BKT * DPAD;             // BQ  x BKPAD
    float* sMx = sP + BQ * BKPAD;            // BQ running max
    float* sZ  = sMx + BQ;                   // BQ running denom
    float* sC  = sZ + BQ;                    // BQ correction factor

    const int t  = threadIdx.x;
    const int bh = blockIdx.x >> 3;          // Sc/BQ == 8 q-tiles
    const int q0 = (blockIdx.x & 7) * BQ;

    const int mask_bytes = g_mask_byte_mode; // uniform across grid

    const size_t qkvbase = (size_t)bh * Sc * Dc;
    const size_t mbase   = (size_t)bh * Sc * Sc;
    const float* Qb = Q + qkvbase;
    const float* Kb = K + qkvbase;
    const float* Vb = V + qkvbase;
    const unsigned int*  MbW = (const unsigned int*)MSK + mbase;   // word bools
    const unsigned char* MbB = (const unsigned char*)MSK + mbase;  // byte bools
    const float* Tb = TW + mbase;
    const float* Ub = DU + mbase;
    float* Ob = O + qkvbase;

    // ---- Load Q tile (coalesced float4) ----
    for (int i = t; i < BQ * (Dc / 4); i += NTHREADS) {
        int q = i >> 4, d4 = i & 15;
        ((float4*)(sQ + q * DPAD))[d4] =
            ((const float4*)(Qb + (size_t)(q0 + q) * Dc))[d4];
    }
    if (t < BQ) { sMx[t] = -INFINITY; sZ[t] = 0.f; }

    const int lane = t & 31;
    const int w    = t >> 5;                 // 8 warps

    // Phase-D mapping: warp w owns q rows [16w, 16w+16); lane owns 8 rows
    // (upper/lower half by lane>>4) x one float4 d-chunk (lane&15).
    const int qb = (w << 4) + ((lane >> 4) << 3);
    const int dc = lane & 15;
    float4 acc[8];
    #pragma unroll
    for (int i = 0; i < 8; i++) acc[i] = make_float4(0.f, 0.f, 0.f, 0.f);

    // Phase-A mapping: 8x4 micro-tile; q rows tq..tq+7, k cols u+16j (striped)
    const int tq = (t >> 4) << 3;            // 0,8,...,120
    const int u  = t & 15;

    __syncthreads();

    const float scale = 0.125f;              // 1/sqrt(64)

    for (int kt = 0; kt < Sc / BKT; kt++) {
        const int k0 = kt * BKT;

        // ---- Load K,V tiles ----
        for (int i = t; i < BKT * (Dc / 4); i += NTHREADS) {
            int k = i >> 4, d4 = i & 15;
            ((float4*)(sK + k * DPAD))[d4] =
                ((const float4*)(Kb + (size_t)(k0 + k) * Dc))[d4];
            ((float4*)(sV + k * DPAD))[d4] =
                ((const float4*)(Vb + (size_t)(k0 + k) * Dc))[d4];
        }
        __syncthreads();

        // ---- Phase A: S = Q K^T (8x4 micro-tile per thread) ----
        {
            float s[8][4];
            #pragma unroll
            for (int i = 0; i < 8; i++)
                #pragma unroll
                for (int j = 0; j < 4; j++) s[i][j] = 0.f;

            // unroll 2 (not 4): keeps K-fragment live set ~32 regs so the
            // whole kernel fits the 128-reg cap without spilling.
            #pragma unroll 2
            for (int d4 = 0; d4 < 16; d4++) {
                float4 kv0 = ((const float4*)(sK + (u +  0) * DPAD))[d4];
                float4 kv1 = ((const float4*)(sK + (u + 16) * DPAD))[d4];
                float4 kv2 = ((const float4*)(sK + (u + 32) * DPAD))[d4];
                float4 kv3 = ((const float4*)(sK + (u + 48) * DPAD))[d4];
                #pragma unroll
                for (int i = 0; i < 8; i++) {
                    float4 qv = ((const float4*)(sQ + (tq + i) * DPAD))[d4];
                    s[i][0] += qv.x*kv0.x + qv.y*kv0.y + qv.z*kv0.z + qv.w*kv0.w;
                    s[i][1] += qv.x*kv1.x + qv.y*kv1.y + qv.z*kv1.z + qv.w*kv1.w;
                    s[i][2] += qv.x*kv2.x + qv.y*kv2.y + qv.z*kv2.z + qv.w*kv2.w;
                    s[i][3] += qv.x*kv3.x + qv.y*kv3.y + qv.z*kv3.z + qv.w*kv3.w;
                }
            }

            if (mask_bytes == 0) {
                #pragma unroll
                for (int i = 0; i < 8; i++) {
                    const unsigned int* mrow = MbW + (size_t)(q0 + tq + i) * Sc + k0;
                    float* prow = sP + (tq + i) * BKPAD;
                    #pragma unroll
                    for (int j = 0; j < 4; j++) {
                        int k = u + 16 * j;
                        prow[k] = mrow[k] ? -1e9f : s[i][j] * scale;
                    }
                }
            } else {
                #pragma unroll
                for (int i = 0; i < 8; i++) {
                    const unsigned char* mrow = MbB + (size_t)(q0 + tq + i) * Sc + k0;
                    float* prow = sP + (tq + i) * BKPAD;
                    #pragma unroll
                    for (int j = 0; j < 4; j++) {
                        int k = u + 16 * j;
                        prow[k] = mrow[k] ? -1e9f : s[i][j] * scale;
                    }
                }
            }
        }
        __syncthreads();

        // ---- Phase B: per-row tile max (2 lanes per row), running max ----
        {
            int r  = t >> 1;
            int p2 = t & 1;
            float mx = -INFINITY;
            #pragma unroll
            for (int k = p2; k < BKT; k += 2) mx = fmaxf(mx, sP[r * BKPAD + k]);
            mx = fmaxf(mx, __shfl_xor_sync(0xffffffffu, mx, 1));
            if (p2 == 0) {
                float mold = sMx[r];
                float mnew = fmaxf(mold, mx);
                sMx[r] = mnew;
                sC[r]  = __expf(mold - mnew);   // 0 on first tile (mold=-inf)
            }
        }
        __syncthreads();

        // ---- Phase C: p=exp(s-m); Z update; fold tw * dropout into P ----
        // warp w owns rows 16w..16w+15; lanes stride k -> coalesced tw/du loads
        {
            #pragma unroll
            for (int r16 = 0; r16 < 16; r16++) {
                int r = (w << 4) + r16;
                float mnew = sMx[r];
                const float* trow = Tb + (size_t)(q0 + r) * Sc + k0;
                const float* urow = Ub + (size_t)(q0 + r) * Sc + k0;
                float sum = 0.f;
                #pragma unroll
                for (int h = 0; h < 2; h++) {
                    int k = lane + 32 * h;
                    float p = __expf(sP[r * BKPAD + k] - mnew);
                    sum += p;
                    float keep = (urow[k] >= 0.5f) ? 2.0f : 0.0f;
                    sP[r * BKPAD + k] = p * trow[k] * keep;
                }
                #pragma unroll
                for (int off = 16; off; off >>= 1)
                    sum += __shfl_xor_sync(0xffffffffu, sum, off);
                if (lane == 0) sZ[r] = sZ[r] * sC[r] + sum;
            }
        }
        __syncthreads();

        // ---- Phase D: acc = acc*c + P @ V (8 q-rows x 1 chunk per lane) ----
        {
            #pragma unroll
            for (int i = 0; i < 8; i++) {
                float c = sC[qb + i];
                acc[i].x *= c; acc[i].y *= c; acc[i].z *= c; acc[i].w *= c;
            }
            // unroll 2 (not 4): limits live V-fragment regs to ~32.
            #pragma unroll 2
            for (int k4 = 0; k4 < BKT / 4; k4++) {
                float4 v0 = ((const float4*)(sV + (4*k4 + 0) * DPAD))[dc];
                float4 v1 = ((const float4*)(sV + (4*k4 + 1) * DPAD))[dc];
                float4 v2 = ((const float4*)(sV + (4*k4 + 2) * DPAD))[dc];
                float4 v3 = ((const float4*)(sV + (4*k4 + 3) * DPAD))[dc];
                #pragma unroll
                for (int i = 0; i < 8; i++) {
                    float4 p = ((const float4*)(sP + (qb + i) * BKPAD))[k4];
                    acc[i].x += p.x*v0.x + p.y*v1.x + p.z*v2.x + p.w*v3.x;
                    acc[i].y += p.x*v0.y + p.y*v1.y + p.z*v2.y + p.w*v3.y;
                    acc[i].z += p.x*v0.z + p.y*v1.z + p.z*v2.z + p.w*v3.z;
                    acc[i].w += p.x*v0.w + p.y*v1.w + p.z*v2.w + p.w*v3.w;
                }
            }
        }
        __syncthreads();
    }

    // ---- Epilogue: out = acc / Z ----
    #pragma unroll
    for (int i = 0; i < 8; i++) {
        float inv = 1.0f / sZ[qb + i];
        float4 o = acc[i];
        o.x *= inv; o.y *= inv; o.z *= inv; o.w *= inv;
        ((float4*)(Ob + (size_t)(q0 + qb + i) * Dc))[dc] = o;
    }
}

extern "C" void kernel_launch(void* const* d_in, const int* in_sizes, int n_in,
                              void* d_out, int out_size) {
    const float* Q  = (const float*)d_in[0];
    const float* K  = (const float*)d_in[1];
    const float* V  = (const float*)d_in[2];
    const void*  M  = d_in[3];               // bool mask — dtype detected on device
    const float* TW = (const float*)d_in[4];
    const float* DU = (const float*)d_in[5];
    float* O = (float*)d_out;

    const size_t smem_bytes =
        (size_t)(BQ * DPAD + 2 * BKT * DPAD + BQ * BKPAD + 3 * BQ) * sizeof(float);

    cudaFuncSetAttribute(attn_flash_kernel,
                         cudaFuncAttributeMaxDynamicSharedMemorySize,
                         (int)smem_bytes);

    // 1) Detect mask storage layout (word-bool vs byte-bool).
    detect_mask_dtype_kernel<<<1, 256>>>((const unsigned int*)M);

    // 2) Flash attention, one CTA per (b, h, 128-row q-tile); 2 CTAs/SM.
    dim3 grid(Bc * Hc * (Sc / BQ));   // 512 blocks
    attn_flash_kernel<<<grid, NTHREADS, smem_bytes>>>(Q, K, V, M, TW, DU, O);
}